// round 5
// baseline (speedup 1.0000x reference)
#include <cuda_runtime.h>
#include <math.h>

#define N_NODES 100000
#define N_EDGES 1600000
#define D 128
#define NEG_SLOPE 0.2f
#define LN_EPS 1e-5f
#define TOT_EDGES (N_EDGES + N_NODES)

// ---------------- device scratch (static; no allocation allowed) ----------------
static __device__ int   g_is64;
static __device__ int   g_deg[N_NODES];
static __device__ float g_wsum[N_NODES];
static __device__ int   g_rowptr[N_NODES + 1];
static __device__ int   g_cursor[N_NODES];
static __device__ int   g_csr_src[TOT_EDGES];
static __device__ float g_csr_ew[TOT_EDGES];
static __device__ __align__(16) float g_h[(size_t)N_NODES * D];  // transformed features
static __device__ __align__(16) float g_a[(size_t)N_NODES * D];  // layer activations
static __device__ float g_alpha_s[N_NODES];
static __device__ float g_alpha_d[N_NODES];
static __device__ float g_ce[2];

// ---------------- helpers ----------------
__device__ __forceinline__ float gelu_exact(float v) {
    return 0.5f * v * (1.0f + erff(v * 0.7071067811865475f));
}
__device__ __forceinline__ float lrelu(float v) {
    return v > 0.0f ? v : NEG_SLOPE * v;
}
__device__ __forceinline__ void edge_sd(const void* ei, int e, int& s, int& d) {
    if (g_is64) {
        const long long* p = (const long long*)ei;
        s = (int)p[e];
        d = (int)p[N_EDGES + e];
    } else {
        const int* p = (const int*)ei;
        s = p[e];
        d = p[N_EDGES + e];
    }
}

// ---------------- dtype detection ----------------
// If edge_index is int64 (little-endian), the odd int32 words are high words of
// nonnegative node ids < 2^31 -> all zero. If int32, they are random node ids.
__global__ void k_detect(const int* __restrict__ ei32) {
    if (threadIdx.x == 0 && blockIdx.x == 0) {
        int orv = 0;
        for (int i = 0; i < 1024; i++) orv |= ei32[2 * i + 1];
        g_is64 = (orv == 0) ? 1 : 0;
    }
}

// ---------------- graph prep ----------------
__global__ void k_init() {
    int i = blockIdx.x * blockDim.x + threadIdx.x;
    if (i < N_NODES) { g_deg[i] = 0; g_wsum[i] = 0.0f; g_cursor[i] = 0; }
}

__global__ void k_hist(const void* __restrict__ ei, const float* __restrict__ ew) {
    int e = blockIdx.x * blockDim.x + threadIdx.x;
    if (e < N_EDGES) {
        int s, d;
        edge_sd(ei, e, s, d);
        atomicAdd(&g_deg[d], 1);
        atomicAdd(&g_wsum[d], ew[e]);
    }
}

// single-block exclusive scan of (deg[i] + 1) -> rowptr
__global__ void k_scan() {
    __shared__ int warp_sums[32];
    __shared__ int s_carry;
    int tid = threadIdx.x;
    int lane = tid & 31, wid = tid >> 5;
    if (tid == 0) { s_carry = 0; g_rowptr[0] = 0; }
    __syncthreads();
    for (int base = 0; base < N_NODES; base += 1024) {
        int i = base + tid;
        int v = (i < N_NODES) ? (g_deg[i] + 1) : 0;
        int x = v;
        #pragma unroll
        for (int o = 1; o < 32; o <<= 1) {
            int y = __shfl_up_sync(0xffffffffu, x, o);
            if (lane >= o) x += y;
        }
        if (lane == 31) warp_sums[wid] = x;
        __syncthreads();
        if (wid == 0) {
            int w = warp_sums[lane];
            #pragma unroll
            for (int o = 1; o < 32; o <<= 1) {
                int y = __shfl_up_sync(0xffffffffu, w, o);
                if (lane >= o) w += y;
            }
            warp_sums[lane] = w;
        }
        __syncthreads();
        int incl = x + (wid > 0 ? warp_sums[wid - 1] : 0) + s_carry;
        if (i < N_NODES) g_rowptr[i + 1] = incl;
        __syncthreads();
        if (tid == 1023) s_carry = incl;
        __syncthreads();
    }
}

__global__ void k_scatter(const void* __restrict__ ei, const float* __restrict__ ew) {
    int e = blockIdx.x * blockDim.x + threadIdx.x;
    if (e < N_EDGES) {
        int s, d;
        edge_sd(ei, e, s, d);
        int pos = g_rowptr[d] + atomicAdd(&g_cursor[d], 1);
        g_csr_src[pos] = s;
        g_csr_ew[pos]  = ew[e];
    }
}

__global__ void k_selfloop() {
    int n = blockIdx.x * blockDim.x + threadIdx.x;
    if (n < N_NODES) {
        int pos = g_rowptr[n + 1] - 1;     // edges occupy [rowptr[n], rowptr[n]+deg)
        g_csr_src[pos] = n;
        int dg = g_deg[n];
        g_csr_ew[pos] = g_wsum[n] / (float)(dg > 0 ? dg : 1);
    }
}

// ce[l] = dot(lin_edge_w[l], att_edge[l]);  2 blocks x 128 threads
__global__ void k_pre(const float* __restrict__ lew, const float* __restrict__ aedge) {
    int l = blockIdx.x;
    int t = threadIdx.x;
    __shared__ float red[4];
    float p = lew[l * D + t] * aedge[l * D + t];
    #pragma unroll
    for (int o = 16; o; o >>= 1) p += __shfl_xor_sync(0xffffffffu, p, o);
    if ((t & 31) == 0) red[t >> 5] = p;
    __syncthreads();
    if (t == 0) g_ce[l] = red[0] + red[1] + red[2] + red[3];
}

// ---------------- GEMM: g_h[N,128] = X[N,128] @ W[128,128] (fp32) ----------------
// 64 rows/block, 256 threads, 8x4 micro-tile, K chunked by 32. 24 KB static smem.
#define BK 32
__global__ void __launch_bounds__(256) k_gemm(const float* __restrict__ Xin,
                                              int use_ga,
                                              const float* __restrict__ Wm) {
    __shared__ float xs[64 * BK];      // [64][32]  8 KB
    __shared__ float ws[BK * 128];     // [32][128] 16 KB
    int tid = threadIdx.x;
    int row0 = blockIdx.x * 64;
    const float* X = use_ga ? g_a : Xin;

    int tx = tid & 31, ty = tid >> 5;  // warp ty owns rows ty*8..+8
    int r0 = ty * 8, c0 = tx * 4;
    float acc[8][4];
    #pragma unroll
    for (int i = 0; i < 8; i++)
        #pragma unroll
        for (int j = 0; j < 4; j++) acc[i][j] = 0.f;

    const float4* X4 = (const float4*)X;
    const float4* W4 = (const float4*)Wm;
    float4* xs4 = (float4*)xs;
    float4* ws4 = (float4*)ws;

    for (int kb = 0; kb < 128 / BK; kb++) {
        int kq0 = kb * (BK / 4);       // float4 column offset into X / row offset base
        // load W chunk [BK][128]: 1024 float4s, 4 per thread
        #pragma unroll
        for (int j = 0; j < 4; j++) {
            int idx = tid + j * 256;               // 0..1023
            int kk = idx >> 5;                     // 0..31
            int c  = idx & 31;                     // float4 col
            ws4[idx] = W4[(size_t)(kb * BK + kk) * 32 + c];
        }
        // load X chunk [64][BK]: 512 float4s, 2 per thread
        #pragma unroll
        for (int j = 0; j < 2; j++) {
            int idx = tid + j * 256;               // 0..511
            int r = idx >> 3;                      // 0..63
            int c = idx & 7;                       // 0..7 (float4 within chunk)
            int gr = row0 + r;
            float4 v = make_float4(0.f, 0.f, 0.f, 0.f);
            if (gr < N_NODES) v = X4[(size_t)gr * 32 + kq0 + c];
            xs4[idx] = v;
        }
        __syncthreads();

        #pragma unroll
        for (int k = 0; k < BK; k++) {
            float4 b = *((const float4*)&ws[k * 128 + c0]);
            #pragma unroll
            for (int i = 0; i < 8; i++) {
                float a = xs[(r0 + i) * BK + k];   // broadcast within warp
                acc[i][0] += a * b.x;
                acc[i][1] += a * b.y;
                acc[i][2] += a * b.z;
                acc[i][3] += a * b.w;
            }
        }
        __syncthreads();
    }

    #pragma unroll
    for (int i = 0; i < 8; i++) {
        int gr = row0 + r0 + i;
        if (gr < N_NODES) {
            *((float4*)&g_h[(size_t)gr * D + c0]) =
                make_float4(acc[i][0], acc[i][1], acc[i][2], acc[i][3]);
        }
    }
}

// alpha_s[n] = h[n].att_src ; alpha_d[n] = h[n].att_dst  (warp per row)
__global__ void __launch_bounds__(256) k_alpha(const float* __restrict__ asrc,
                                               const float* __restrict__ adst) {
    int warp = (blockIdx.x * 256 + threadIdx.x) >> 5;
    int lane = threadIdx.x & 31;
    if (warp >= N_NODES) return;
    float4 hv = ((const float4*)g_h)[(size_t)warp * 32 + lane];
    float4 s4 = ((const float4*)asrc)[lane];
    float4 d4 = ((const float4*)adst)[lane];
    float ss = hv.x * s4.x + hv.y * s4.y + hv.z * s4.z + hv.w * s4.w;
    float dd = hv.x * d4.x + hv.y * d4.y + hv.z * d4.z + hv.w * d4.w;
    #pragma unroll
    for (int o = 16; o; o >>= 1) {
        ss += __shfl_xor_sync(0xffffffffu, ss, o);
        dd += __shfl_xor_sync(0xffffffffu, dd, o);
    }
    if (lane == 0) { g_alpha_s[warp] = ss; g_alpha_d[warp] = dd; }
}

// softmax-weighted aggregation + bias + GELU -> g_a; one warp per destination node.
__global__ void __launch_bounds__(256) k_agg(int l, const float* __restrict__ bias_l) {
    int warp = (blockIdx.x * 256 + threadIdx.x) >> 5;
    int lane = threadIdx.x & 31;
    if (warp >= N_NODES) return;
    int n = warp;
    int start = g_rowptr[n], end = g_rowptr[n + 1];
    float ad = g_alpha_d[n];
    float ce = g_ce[l];

    // pass 1: online max + sum-exp
    float m = -1e30f, z = 0.f;
    for (int e = start + lane; e < end; e += 32) {
        int s = g_csr_src[e];
        float lg = lrelu(g_alpha_s[s] + ad + ce * g_csr_ew[e]);
        if (lg > m) { z = z * __expf(m - lg) + 1.0f; m = lg; }
        else        { z += __expf(lg - m); }
    }
    #pragma unroll
    for (int o = 16; o; o >>= 1) {
        float mo = __shfl_xor_sync(0xffffffffu, m, o);
        float zo = __shfl_xor_sync(0xffffffffu, z, o);
        float mn = fmaxf(m, mo);
        z = z * __expf(m - mn) + zo * __expf(mo - mn);
        m = mn;
    }
    float inv_z = 1.0f / z;

    // pass 2: accumulate h[src] * coef  (4-way unrolled warp-wide float4 gather)
    float4 acc = make_float4(0.f, 0.f, 0.f, 0.f);
    const float4* h4 = (const float4*)g_h;
    int e = start;
    for (; e + 4 <= end; e += 4) {
        int s0 = g_csr_src[e],     s1 = g_csr_src[e + 1];
        int s2 = g_csr_src[e + 2], s3 = g_csr_src[e + 3];
        float w0 = g_csr_ew[e],     w1 = g_csr_ew[e + 1];
        float w2 = g_csr_ew[e + 2], w3 = g_csr_ew[e + 3];
        float4 h0 = h4[(size_t)s0 * 32 + lane];
        float4 h1 = h4[(size_t)s1 * 32 + lane];
        float4 h2 = h4[(size_t)s2 * 32 + lane];
        float4 h3 = h4[(size_t)s3 * 32 + lane];
        float c0 = __expf(lrelu(g_alpha_s[s0] + ad + ce * w0) - m) * inv_z;
        float c1 = __expf(lrelu(g_alpha_s[s1] + ad + ce * w1) - m) * inv_z;
        float c2 = __expf(lrelu(g_alpha_s[s2] + ad + ce * w2) - m) * inv_z;
        float c3 = __expf(lrelu(g_alpha_s[s3] + ad + ce * w3) - m) * inv_z;
        acc.x += c0 * h0.x + c1 * h1.x + c2 * h2.x + c3 * h3.x;
        acc.y += c0 * h0.y + c1 * h1.y + c2 * h2.y + c3 * h3.y;
        acc.z += c0 * h0.z + c1 * h1.z + c2 * h2.z + c3 * h3.z;
        acc.w += c0 * h0.w + c1 * h1.w + c2 * h2.w + c3 * h3.w;
    }
    for (; e < end; e++) {
        int s = g_csr_src[e];
        float coef = __expf(lrelu(g_alpha_s[s] + ad + ce * g_csr_ew[e]) - m) * inv_z;
        float4 hv = h4[(size_t)s * 32 + lane];
        acc.x += coef * hv.x;
        acc.y += coef * hv.y;
        acc.z += coef * hv.z;
        acc.w += coef * hv.w;
    }

    float4 b = ((const float4*)bias_l)[lane];
    float4 r;
    r.x = gelu_exact(acc.x + b.x);
    r.y = gelu_exact(acc.y + b.y);
    r.z = gelu_exact(acc.z + b.z);
    r.w = gelu_exact(acc.w + b.w);
    ((float4*)g_a)[(size_t)n * 32 + lane] = r;
}

// out = LayerNorm(x + g_a) * gamma + beta  (warp per row)
__global__ void __launch_bounds__(256) k_ln(const float* __restrict__ X,
                                            const float* __restrict__ gamma,
                                            const float* __restrict__ beta,
                                            float* __restrict__ out) {
    int warp = (blockIdx.x * 256 + threadIdx.x) >> 5;
    int lane = threadIdx.x & 31;
    if (warp >= N_NODES) return;
    float4 xv = ((const float4*)X)[(size_t)warp * 32 + lane];
    float4 av = ((const float4*)g_a)[(size_t)warp * 32 + lane];
    float4 v = make_float4(xv.x + av.x, xv.y + av.y, xv.z + av.z, xv.w + av.w);
    float s = v.x + v.y + v.z + v.w;
    #pragma unroll
    for (int o = 16; o; o >>= 1) s += __shfl_xor_sync(0xffffffffu, s, o);
    float mu = s * (1.0f / 128.0f);
    float dx = v.x - mu, dy = v.y - mu, dz = v.z - mu, dw = v.w - mu;
    float q = dx * dx + dy * dy + dz * dz + dw * dw;
    #pragma unroll
    for (int o = 16; o; o >>= 1) q += __shfl_xor_sync(0xffffffffu, q, o);
    float var = q * (1.0f / 128.0f);
    float inv = rsqrtf(var + LN_EPS);
    float4 g = ((const float4*)gamma)[lane];
    float4 b = ((const float4*)beta)[lane];
    float4 r;
    r.x = dx * inv * g.x + b.x;
    r.y = dy * inv * g.y + b.y;
    r.z = dz * inv * g.z + b.z;
    r.w = dw * inv * g.w + b.w;
    ((float4*)out)[(size_t)warp * 32 + lane] = r;
}

// ---------------- launch (kernel launches only; no other CUDA API calls) ----------------
extern "C" void kernel_launch(void* const* d_in, const int* in_sizes, int n_in,
                              void* d_out, int out_size) {
    (void)in_sizes; (void)n_in; (void)out_size;
    const float* x     = (const float*)d_in[0];
    const void*  ei    = d_in[1];
    const float* ew    = (const float*)d_in[2];
    const float* W     = (const float*)d_in[3];
    const float* asrc  = (const float*)d_in[4];
    const float* adst  = (const float*)d_in[5];
    const float* lew   = (const float*)d_in[6];
    const float* aedge = (const float*)d_in[7];
    const float* bias  = (const float*)d_in[8];
    const float* gamma = (const float*)d_in[9];
    const float* beta  = (const float*)d_in[10];
    float*       out   = (float*)d_out;

    const int TB = 256;
    int nb_nodes = (N_NODES + TB - 1) / TB;
    int nb_edges = (N_EDGES + TB - 1) / TB;
    int nb_warp  = (N_NODES + 7) / 8;
    int nb_gemm  = (N_NODES + 63) / 64;

    // graph prep
    k_detect<<<1, 32>>>((const int*)ei);
    k_init<<<nb_nodes, TB>>>();
    k_hist<<<nb_edges, TB>>>(ei, ew);
    k_scan<<<1, 1024>>>();
    k_scatter<<<nb_edges, TB>>>(ei, ew);
    k_selfloop<<<nb_nodes, TB>>>();
    k_pre<<<2, 128>>>(lew, aedge);

    // layer 0: x -> g_a
    k_gemm<<<nb_gemm, TB>>>(x, 0, W);
    k_alpha<<<nb_warp, TB>>>(asrc, adst);
    k_agg<<<nb_warp, TB>>>(0, bias);

    // layer 1: g_a -> g_a
    k_gemm<<<nb_gemm, TB>>>(x, 1, W + D * D);
    k_alpha<<<nb_warp, TB>>>(asrc + D, adst + D);
    k_agg<<<nb_warp, TB>>>(1, bias + D);

    // residual + layernorm
    k_ln<<<nb_warp, TB>>>(x, gamma, beta, out);
}

// round 6
// speedup vs baseline: 1.8119x; 1.8119x over previous
#include <cuda_runtime.h>
#include <math.h>

#define N_NODES 100000
#define N_EDGES 1600000
#define D 128
#define NEG_SLOPE 0.2f
#define LN_EPS 1e-5f
#define TOT_EDGES (N_EDGES + N_NODES)
#define SCAN_B 1024
#define SCAN_NB ((N_NODES + SCAN_B - 1) / SCAN_B)   // 98

// ---------------- device scratch (static; no allocation allowed) ----------------
static __device__ int   g_is64;
static __device__ int   g_deg[N_NODES];
static __device__ float g_wsum[N_NODES];
static __device__ int   g_rowptr[N_NODES + 1];
static __device__ int   g_cursor[N_NODES];
static __device__ int   g_bsum[SCAN_NB];
static __device__ int   g_boff[SCAN_NB];
static __device__ int   g_csr_src[TOT_EDGES];
static __device__ float g_csr_ew[TOT_EDGES];
static __device__ __align__(16) float g_h[(size_t)N_NODES * D];  // transformed features
static __device__ __align__(16) float g_a[(size_t)N_NODES * D];  // layer activations
static __device__ float g_alpha_s[N_NODES];
static __device__ float g_alpha_d[N_NODES];
static __device__ float g_ce[2];

// ---------------- helpers ----------------
__device__ __forceinline__ float gelu_exact(float v) {
    return 0.5f * v * (1.0f + erff(v * 0.7071067811865475f));
}
__device__ __forceinline__ float lrelu(float v) {
    return v > 0.0f ? v : NEG_SLOPE * v;
}
__device__ __forceinline__ void edge_sd(const void* ei, int e, int& s, int& d) {
    if (g_is64) {
        const long long* p = (const long long*)ei;
        s = (int)p[e];
        d = (int)p[N_EDGES + e];
    } else {
        const int* p = (const int*)ei;
        s = p[e];
        d = p[N_EDGES + e];
    }
}

// ---------------- dtype detection ----------------
__global__ void k_detect(const int* __restrict__ ei32) {
    int lane = threadIdx.x;
    int orv = 0;
    for (int i = lane; i < 1024; i += 32) orv |= ei32[2 * i + 1];
    #pragma unroll
    for (int o = 16; o; o >>= 1) orv |= __shfl_xor_sync(0xffffffffu, orv, o);
    if (lane == 0) g_is64 = (orv == 0) ? 1 : 0;
}

// ---------------- graph prep ----------------
__global__ void k_init() {
    int i = blockIdx.x * blockDim.x + threadIdx.x;
    if (i < N_NODES) { g_deg[i] = 0; g_wsum[i] = 0.0f; g_cursor[i] = 0; }
}

__global__ void k_hist(const void* __restrict__ ei, const float* __restrict__ ew) {
    int e = blockIdx.x * blockDim.x + threadIdx.x;
    if (e < N_EDGES) {
        int s, d;
        edge_sd(ei, e, s, d);
        atomicAdd(&g_deg[d], 1);
        atomicAdd(&g_wsum[d], ew[e]);
    }
}

// ---- 3-phase multi-block exclusive scan of (deg[i]+1) -> rowptr ----
// phase A: per-block sums
__global__ void __launch_bounds__(SCAN_B) k_scanA() {
    __shared__ int wsum[32];
    int tid = threadIdx.x, lane = tid & 31, wid = tid >> 5;
    int i = blockIdx.x * SCAN_B + tid;
    int v = (i < N_NODES) ? (g_deg[i] + 1) : 0;
    #pragma unroll
    for (int o = 16; o; o >>= 1) v += __shfl_xor_sync(0xffffffffu, v, o);
    if (lane == 0) wsum[wid] = v;
    __syncthreads();
    if (wid == 0) {
        int w = wsum[lane];
        #pragma unroll
        for (int o = 16; o; o >>= 1) w += __shfl_xor_sync(0xffffffffu, w, o);
        if (lane == 0) g_bsum[blockIdx.x] = w;
    }
}

// phase B: exclusive scan of SCAN_NB block sums (one block, 128 threads)
__global__ void k_scanB() {
    __shared__ int wsum[4];
    int tid = threadIdx.x, lane = tid & 31, wid = tid >> 5;
    int v = (tid < SCAN_NB) ? g_bsum[tid] : 0;
    int x = v;
    #pragma unroll
    for (int o = 1; o < 32; o <<= 1) {
        int y = __shfl_up_sync(0xffffffffu, x, o);
        if (lane >= o) x += y;
    }
    if (lane == 31) wsum[wid] = x;
    __syncthreads();
    int base = 0;
    for (int w = 0; w < wid; w++) base += wsum[w];
    if (tid < SCAN_NB) g_boff[tid] = base + x - v;   // exclusive
}

// phase C: per-block local exclusive scan + offset; write rowptr[i+1] (inclusive)
__global__ void __launch_bounds__(SCAN_B) k_scanC() {
    __shared__ int wsum[32];
    int tid = threadIdx.x, lane = tid & 31, wid = tid >> 5;
    int i = blockIdx.x * SCAN_B + tid;
    int v = (i < N_NODES) ? (g_deg[i] + 1) : 0;
    int x = v;
    #pragma unroll
    for (int o = 1; o < 32; o <<= 1) {
        int y = __shfl_up_sync(0xffffffffu, x, o);
        if (lane >= o) x += y;
    }
    if (lane == 31) wsum[wid] = x;
    __syncthreads();
    if (wid == 0) {
        int w = wsum[lane];
        #pragma unroll
        for (int o = 1; o < 32; o <<= 1) {
            int y = __shfl_up_sync(0xffffffffu, w, o);
            if (lane >= o) w += y;
        }
        wsum[lane] = w;
    }
    __syncthreads();
    int incl = x + (wid > 0 ? wsum[wid - 1] : 0) + g_boff[blockIdx.x];
    if (i < N_NODES) g_rowptr[i + 1] = incl;
    if (i == 0) g_rowptr[0] = 0;
}

__global__ void k_scatter(const void* __restrict__ ei, const float* __restrict__ ew) {
    int e = blockIdx.x * blockDim.x + threadIdx.x;
    if (e < N_EDGES) {
        int s, d;
        edge_sd(ei, e, s, d);
        int pos = g_rowptr[d] + atomicAdd(&g_cursor[d], 1);
        g_csr_src[pos] = s;
        g_csr_ew[pos]  = ew[e];
    }
}

__global__ void k_selfloop() {
    int n = blockIdx.x * blockDim.x + threadIdx.x;
    if (n < N_NODES) {
        int pos = g_rowptr[n + 1] - 1;
        g_csr_src[pos] = n;
        int dg = g_deg[n];
        g_csr_ew[pos] = g_wsum[n] / (float)(dg > 0 ? dg : 1);
    }
}

// ce[l] = dot(lin_edge_w[l], att_edge[l])
__global__ void k_pre(const float* __restrict__ lew, const float* __restrict__ aedge) {
    int l = blockIdx.x;
    int t = threadIdx.x;
    __shared__ float red[4];
    float p = lew[l * D + t] * aedge[l * D + t];
    #pragma unroll
    for (int o = 16; o; o >>= 1) p += __shfl_xor_sync(0xffffffffu, p, o);
    if ((t & 31) == 0) red[t >> 5] = p;
    __syncthreads();
    if (t == 0) g_ce[l] = red[0] + red[1] + red[2] + red[3];
}

// ---------------- GEMM + fused alpha epilogue ----------------
// g_h[N,128] = X @ W ; alpha_s/alpha_d from register accumulators.
// 64 rows/block, 256 threads, 8x4 micro-tile, K chunked by 32. 24 KB static smem.
#define BK 32
__global__ void __launch_bounds__(256) k_gemm(const float* __restrict__ Xin,
                                              int use_ga,
                                              const float* __restrict__ Wm,
                                              const float* __restrict__ asrc_l,
                                              const float* __restrict__ adst_l) {
    __shared__ float xs[64 * BK];
    __shared__ float ws[BK * 128];
    int tid = threadIdx.x;
    int row0 = blockIdx.x * 64;
    const float* X = use_ga ? g_a : Xin;

    int tx = tid & 31, ty = tid >> 5;
    int r0 = ty * 8, c0 = tx * 4;
    float acc[8][4];
    #pragma unroll
    for (int i = 0; i < 8; i++)
        #pragma unroll
        for (int j = 0; j < 4; j++) acc[i][j] = 0.f;

    const float4* X4 = (const float4*)X;
    const float4* W4 = (const float4*)Wm;
    float4* xs4 = (float4*)xs;
    float4* ws4 = (float4*)ws;

    for (int kb = 0; kb < 128 / BK; kb++) {
        int kq0 = kb * (BK / 4);
        #pragma unroll
        for (int j = 0; j < 4; j++) {
            int idx = tid + j * 256;
            int kk = idx >> 5;
            int c  = idx & 31;
            ws4[idx] = W4[(size_t)(kb * BK + kk) * 32 + c];
        }
        #pragma unroll
        for (int j = 0; j < 2; j++) {
            int idx = tid + j * 256;
            int r = idx >> 3;
            int c = idx & 7;
            int gr = row0 + r;
            float4 v = make_float4(0.f, 0.f, 0.f, 0.f);
            if (gr < N_NODES) v = X4[(size_t)gr * 32 + kq0 + c];
            xs4[idx] = v;
        }
        __syncthreads();

        #pragma unroll
        for (int k = 0; k < BK; k++) {
            float4 b = *((const float4*)&ws[k * 128 + c0]);
            #pragma unroll
            for (int i = 0; i < 8; i++) {
                float a = xs[(r0 + i) * BK + k];
                acc[i][0] += a * b.x;
                acc[i][1] += a * b.y;
                acc[i][2] += a * b.z;
                acc[i][3] += a * b.w;
            }
        }
        __syncthreads();
    }

    // store H + fused alpha (warp holds full rows)
    float4 s4 = ((const float4*)asrc_l)[tx];
    float4 d4 = ((const float4*)adst_l)[tx];
    #pragma unroll
    for (int i = 0; i < 8; i++) {
        int gr = row0 + r0 + i;
        float ss = acc[i][0] * s4.x + acc[i][1] * s4.y + acc[i][2] * s4.z + acc[i][3] * s4.w;
        float dd = acc[i][0] * d4.x + acc[i][1] * d4.y + acc[i][2] * d4.z + acc[i][3] * d4.w;
        #pragma unroll
        for (int o = 16; o; o >>= 1) {
            ss += __shfl_xor_sync(0xffffffffu, ss, o);
            dd += __shfl_xor_sync(0xffffffffu, dd, o);
        }
        if (gr < N_NODES) {
            *((float4*)&g_h[(size_t)gr * D + c0]) =
                make_float4(acc[i][0], acc[i][1], acc[i][2], acc[i][3]);
            if (tx == 0) { g_alpha_s[gr] = ss; g_alpha_d[gr] = dd; }
        }
    }
}

// softmax-weighted aggregation + bias + GELU; one warp per destination node.
// If is_final: fuse residual + LayerNorm and write to out; else write to g_a.
__global__ void __launch_bounds__(256) k_agg(int l, const float* __restrict__ bias_l,
                                             int is_final,
                                             const float* __restrict__ X,
                                             const float* __restrict__ gamma,
                                             const float* __restrict__ beta,
                                             float* __restrict__ out) {
    int warp = (blockIdx.x * 256 + threadIdx.x) >> 5;
    int lane = threadIdx.x & 31;
    if (warp >= N_NODES) return;
    int n = warp;
    int start = g_rowptr[n], end = g_rowptr[n + 1];
    float ad = g_alpha_d[n];
    float ce = g_ce[l];

    // pass 1: online max + sum-exp
    float m = -1e30f, z = 0.f;
    for (int e = start + lane; e < end; e += 32) {
        int s = g_csr_src[e];
        float lg = lrelu(g_alpha_s[s] + ad + ce * g_csr_ew[e]);
        if (lg > m) { z = z * __expf(m - lg) + 1.0f; m = lg; }
        else        { z += __expf(lg - m); }
    }
    #pragma unroll
    for (int o = 16; o; o >>= 1) {
        float mo = __shfl_xor_sync(0xffffffffu, m, o);
        float zo = __shfl_xor_sync(0xffffffffu, z, o);
        float mn = fmaxf(m, mo);
        z = z * __expf(m - mn) + zo * __expf(mo - mn);
        m = mn;
    }
    float inv_z = 1.0f / z;

    // pass 2: 4-way unrolled warp-wide float4 gather
    float4 acc = make_float4(0.f, 0.f, 0.f, 0.f);
    const float4* h4 = (const float4*)g_h;
    int e = start;
    for (; e + 4 <= end; e += 4) {
        int s0 = g_csr_src[e],     s1 = g_csr_src[e + 1];
        int s2 = g_csr_src[e + 2], s3 = g_csr_src[e + 3];
        float w0 = g_csr_ew[e],     w1 = g_csr_ew[e + 1];
        float w2 = g_csr_ew[e + 2], w3 = g_csr_ew[e + 3];
        float4 h0 = h4[(size_t)s0 * 32 + lane];
        float4 h1 = h4[(size_t)s1 * 32 + lane];
        float4 h2 = h4[(size_t)s2 * 32 + lane];
        float4 h3 = h4[(size_t)s3 * 32 + lane];
        float c0 = __expf(lrelu(g_alpha_s[s0] + ad + ce * w0) - m) * inv_z;
        float c1 = __expf(lrelu(g_alpha_s[s1] + ad + ce * w1) - m) * inv_z;
        float c2 = __expf(lrelu(g_alpha_s[s2] + ad + ce * w2) - m) * inv_z;
        float c3 = __expf(lrelu(g_alpha_s[s3] + ad + ce * w3) - m) * inv_z;
        acc.x += c0 * h0.x + c1 * h1.x + c2 * h2.x + c3 * h3.x;
        acc.y += c0 * h0.y + c1 * h1.y + c2 * h2.y + c3 * h3.y;
        acc.z += c0 * h0.z + c1 * h1.z + c2 * h2.z + c3 * h3.z;
        acc.w += c0 * h0.w + c1 * h1.w + c2 * h2.w + c3 * h3.w;
    }
    for (; e < end; e++) {
        int s = g_csr_src[e];
        float coef = __expf(lrelu(g_alpha_s[s] + ad + ce * g_csr_ew[e]) - m) * inv_z;
        float4 hv = h4[(size_t)s * 32 + lane];
        acc.x += coef * hv.x;
        acc.y += coef * hv.y;
        acc.z += coef * hv.z;
        acc.w += coef * hv.w;
    }

    float4 b = ((const float4*)bias_l)[lane];
    float4 r;
    r.x = gelu_exact(acc.x + b.x);
    r.y = gelu_exact(acc.y + b.y);
    r.z = gelu_exact(acc.z + b.z);
    r.w = gelu_exact(acc.w + b.w);

    if (!is_final) {
        ((float4*)g_a)[(size_t)n * 32 + lane] = r;
        return;
    }

    // fused residual + LayerNorm
    float4 xv = ((const float4*)X)[(size_t)n * 32 + lane];
    float4 v = make_float4(xv.x + r.x, xv.y + r.y, xv.z + r.z, xv.w + r.w);
    float s = v.x + v.y + v.z + v.w;
    #pragma unroll
    for (int o = 16; o; o >>= 1) s += __shfl_xor_sync(0xffffffffu, s, o);
    float mu = s * (1.0f / 128.0f);
    float dx = v.x - mu, dy = v.y - mu, dz = v.z - mu, dw = v.w - mu;
    float q = dx * dx + dy * dy + dz * dz + dw * dw;
    #pragma unroll
    for (int o = 16; o; o >>= 1) q += __shfl_xor_sync(0xffffffffu, q, o);
    float var = q * (1.0f / 128.0f);
    float inv = rsqrtf(var + LN_EPS);
    float4 g = ((const float4*)gamma)[lane];
    float4 bb = ((const float4*)beta)[lane];
    float4 o4;
    o4.x = dx * inv * g.x + bb.x;
    o4.y = dy * inv * g.y + bb.y;
    o4.z = dz * inv * g.z + bb.z;
    o4.w = dw * inv * g.w + bb.w;
    ((float4*)out)[(size_t)n * 32 + lane] = o4;
}

// ---------------- launch (kernel launches only) ----------------
extern "C" void kernel_launch(void* const* d_in, const int* in_sizes, int n_in,
                              void* d_out, int out_size) {
    (void)in_sizes; (void)n_in; (void)out_size;
    const float* x     = (const float*)d_in[0];
    const void*  ei    = d_in[1];
    const float* ew    = (const float*)d_in[2];
    const float* W     = (const float*)d_in[3];
    const float* asrc  = (const float*)d_in[4];
    const float* adst  = (const float*)d_in[5];
    const float* lew   = (const float*)d_in[6];
    const float* aedge = (const float*)d_in[7];
    const float* bias  = (const float*)d_in[8];
    const float* gamma = (const float*)d_in[9];
    const float* beta  = (const float*)d_in[10];
    float*       out   = (float*)d_out;

    const int TB = 256;
    int nb_nodes = (N_NODES + TB - 1) / TB;
    int nb_edges = (N_EDGES + TB - 1) / TB;
    int nb_warp  = (N_NODES + 7) / 8;
    int nb_gemm  = (N_NODES + 63) / 64;

    // graph prep
    k_detect<<<1, 32>>>((const int*)ei);
    k_init<<<nb_nodes, TB>>>();
    k_hist<<<nb_edges, TB>>>(ei, ew);
    k_scanA<<<SCAN_NB, SCAN_B>>>();
    k_scanB<<<1, 128>>>();
    k_scanC<<<SCAN_NB, SCAN_B>>>();
    k_scatter<<<nb_edges, TB>>>(ei, ew);
    k_selfloop<<<nb_nodes, TB>>>();
    k_pre<<<2, 128>>>(lew, aedge);

    // layer 0: x -> g_a
    k_gemm<<<nb_gemm, TB>>>(x, 0, W, asrc, adst);
    k_agg<<<nb_warp, TB>>>(0, bias, 0, x, gamma, beta, out);

    // layer 1: g_a -> out (fused residual + LN)
    k_gemm<<<nb_gemm, TB>>>(x, 1, W + D * D, asrc + D, adst + D);
    k_agg<<<nb_warp, TB>>>(1, bias + D, 1, x, gamma, beta, out);
}